// round 14
// baseline (speedup 1.0000x reference)
#include <cuda_runtime.h>
#include <cuda_bf16.h>
#include <cstdint>

#define NN   50000
#define NP   50128           // padded rows (OOB-safe cp.async for last block)
#define FD   128
#define RR   3
#define EE   800000
#define OUTD 64
#define NNFD ((size_t)NN * FD)
#define WLAYER (RR * FD * FD)          // 49152 per hidden layer
#define WHID   (4 * WLAYER)            // hidden layers 0..3
#define WFUSE  (RR * FD * OUTD)        // fused layer-4 weight [384][64]
#define WTOT   (WHID + WFUSE)
#define STILE  4096                    // scan tile (1024 thr x 4)
#define NB     ((NN + STILE - 1) / STILE)   // 13 tiles / relation
#define RPS    (NN + 4)                // rowptr row stride, multiple of 4 -> int4-aligned

// ---------------- static device scratch ----------------
__device__ float4 g_h0[NNFD / 4];
__device__ float4 g_h1[NNFD / 4];
__device__ uint2  g_aggh[(size_t)RR * NP * 32];   // bf16 hi image of agg [r][row][128]
__device__ uint2  g_aggl[(size_t)RR * NP * 32];   // bf16 lo image
__device__ __nv_bfloat16 g_wh[WTOT];              // weight hi ([K][N] row-major per layer)
__device__ __nv_bfloat16 g_wl[WTOT];
__device__ float  g_biasm[4 * FD];                // folded mean bias, layers 0..3
__device__ float  g_biasf[OUTD];                  // fused final bias
__device__ int    g_rowptr[RR * RPS];             // per-relation rowptr (element NN = total)
__device__ int    g_wptr[RR * NN];                // working copy for fill's slot atomics
__device__ int    g_cnt[2 * RR * NN];             // [outdeg | indeg] contiguous
__device__ int    g_bsum[RR * NB];                // per-tile sums
__device__ int    g_bpre[RR * NB];                // per-tile exclusive prefixes
__device__ int2   g_edge[(size_t)RR * EE];        // {src*32 (float4 units), coef bits}, CSR by dst

#define ODEG(r, n) g_cnt[(r) * NN + (n)]
#define IDEG(r, n) g_cnt[RR * NN + (r) * NN + (n)]

// ---------------- ptx helpers (baseline PTX only) ----------------
__device__ __forceinline__ uint32_t smem_u32(const void* p) {
    uint32_t a;
    asm("{ .reg .u64 t; cvta.to.shared.u64 t, %1; cvt.u32.u64 %0, t; }" : "=r"(a) : "l"(p));
    return a;
}
__device__ __forceinline__ void cpasync16(uint32_t sdst, const void* gsrc) {
    asm volatile("cp.async.cg.shared.global [%0], [%1], 16;" :: "r"(sdst), "l"(gsrc) : "memory");
}
__device__ __forceinline__ void cp_commit() {
    asm volatile("cp.async.commit_group;" ::: "memory");
}
template <int N>
__device__ __forceinline__ void cp_wait() {
    asm volatile("cp.async.wait_group %0;" :: "n"(N) : "memory");
}
__device__ __forceinline__ void ldsm_x4(uint32_t* r, uint32_t addr) {
    asm volatile("ldmatrix.sync.aligned.m8n8.x4.shared.b16 {%0,%1,%2,%3}, [%4];"
                 : "=r"(r[0]), "=r"(r[1]), "=r"(r[2]), "=r"(r[3]) : "r"(addr));
}
__device__ __forceinline__ void ldsm_x4t(uint32_t* r, uint32_t addr) {
    asm volatile("ldmatrix.sync.aligned.m8n8.x4.trans.shared.b16 {%0,%1,%2,%3}, [%4];"
                 : "=r"(r[0]), "=r"(r[1]), "=r"(r[2]), "=r"(r[3]) : "r"(addr));
}
__device__ __forceinline__ void mma16816(float* d, const uint32_t* a, const uint32_t* b) {
    asm volatile("mma.sync.aligned.m16n8k16.row.col.f32.bf16.bf16.f32 "
                 "{%0,%1,%2,%3},{%4,%5,%6,%7},{%8,%9},{%0,%1,%2,%3};"
                 : "+f"(d[0]), "+f"(d[1]), "+f"(d[2]), "+f"(d[3])
                 : "r"(a[0]), "r"(a[1]), "r"(a[2]), "r"(a[3]), "r"(b[0]), "r"(b[1]));
}

// ---------------- degree histogram (4 edges / thread, int4 loads) ----------------
__global__ void k_degree(const int4* __restrict__ src4, const int4* __restrict__ dst4) {
    int i = blockIdx.x * blockDim.x + threadIdx.x;
    int r = blockIdx.y;
    if (i < EE / 4) {
        int4 s = __ldg(&src4[(size_t)r * (EE / 4) + i]);
        int4 d = __ldg(&dst4[(size_t)r * (EE / 4) + i]);
        atomicAdd(&ODEG(r, s.x), 1); atomicAdd(&ODEG(r, s.y), 1);
        atomicAdd(&ODEG(r, s.z), 1); atomicAdd(&ODEG(r, s.w), 1);
        atomicAdd(&IDEG(r, d.x), 1); atomicAdd(&IDEG(r, d.y), 1);
        atomicAdd(&IDEG(r, d.z), 1); atomicAdd(&IDEG(r, d.w), 1);
    }
}

// ---------------- scan phase 1: per-tile sums (coalesced int4) ----------------
__global__ __launch_bounds__(1024) void k_scan1() {
    int r = blockIdx.y, b = blockIdx.x, t = threadIdx.x;
    int lane = t & 31, wid = t >> 5;
    __shared__ int wsum[32];
    int base = b * STILE + t * 4;
    int s = 0;
    if (base + 3 < NN) {
        int4 v = *(const int4*)&IDEG(r, base);
        s = v.x + v.y + v.z + v.w;
    } else {
        #pragma unroll
        for (int j = 0; j < 4; j++)
            if (base + j < NN) s += IDEG(r, base + j);
    }
    #pragma unroll
    for (int d = 16; d > 0; d >>= 1) s += __shfl_down_sync(0xffffffffu, s, d);
    if (lane == 0) wsum[wid] = s;
    __syncthreads();
    if (wid == 0) {
        s = wsum[lane];
        #pragma unroll
        for (int d = 16; d > 0; d >>= 1) s += __shfl_down_sync(0xffffffffu, s, d);
        if (lane == 0) g_bsum[r * NB + b] = s;
    }
}

// ---------------- scan phase 2: scan the 13 tile sums per relation ----------------
__global__ void k_scan2() {
    int r = threadIdx.x;
    if (r < RR) {
        int pre = 0;
        #pragma unroll
        for (int i = 0; i < NB; i++) {
            int v = g_bsum[r * NB + i];
            g_bpre[r * NB + i] = pre;
            pre += v;
        }
        g_rowptr[r * RPS + NN] = pre;
    }
}

// ---------------- scan phase 3: block-local exclusive scan + tile offset ----------------
__global__ __launch_bounds__(1024) void k_scan3() {
    int r = blockIdx.y, b = blockIdx.x, t = threadIdx.x;
    int lane = t & 31, wid = t >> 5;
    __shared__ int wsum[32];
    int base = b * STILE + t * 4;
    int v0 = 0, v1 = 0, v2 = 0, v3 = 0;
    if (base + 3 < NN) {
        int4 v = *(const int4*)&IDEG(r, base);
        v0 = v.x; v1 = v.y; v2 = v.z; v3 = v.w;
    } else {
        if (base + 0 < NN) v0 = IDEG(r, base + 0);
        if (base + 1 < NN) v1 = IDEG(r, base + 1);
        if (base + 2 < NN) v2 = IDEG(r, base + 2);
        if (base + 3 < NN) v3 = IDEG(r, base + 3);
    }
    int ts = v0 + v1 + v2 + v3;
    int incl = ts;
    #pragma unroll
    for (int d = 1; d < 32; d <<= 1) {
        int u = __shfl_up_sync(0xffffffffu, incl, d);
        if (lane >= d) incl += u;
    }
    if (lane == 31) wsum[wid] = incl;
    __syncthreads();
    if (wid == 0) {
        int w = wsum[lane];
        int wi = w;
        #pragma unroll
        for (int d = 1; d < 32; d <<= 1) {
            int u = __shfl_up_sync(0xffffffffu, wi, d);
            if (lane >= d) wi += u;
        }
        wsum[lane] = wi - w;
    }
    __syncthreads();
    int pre = g_bpre[r * NB + b] + wsum[wid] + incl - ts;
    int p0 = pre, p1 = p0 + v0, p2 = p1 + v1, p3 = p2 + v2;
    if (base + 3 < NN) {
        int4 pv = {p0, p1, p2, p3};
        *(int4*)&g_rowptr[r * RPS + base] = pv;
        *(int4*)&g_wptr[r * NN + base] = pv;
    } else {
        int pp[4] = {p0, p1, p2, p3};
        #pragma unroll
        for (int j = 0; j < 4; j++)
            if (base + j < NN) {
                g_rowptr[r * RPS + base + j] = pp[j];
                g_wptr[r * NN + base + j] = pp[j];
            }
    }
}

// ---------------- counting-sort fill: direct slot atomic + single int2 store ----------------
__global__ void k_fill(const int* __restrict__ src, const int* __restrict__ dst) {
    int e = blockIdx.x * blockDim.x + threadIdx.x;
    int r = blockIdx.y;
    if (e < EE) {
        int s = src[(size_t)r * EE + e];
        int d = dst[(size_t)r * EE + e];
        int pos = atomicAdd(&g_wptr[r * NN + d], 1);
        float no = rsqrtf(fmaxf((float)ODEG(r, s), 1.f));
        float ni = rsqrtf(fmaxf((float)IDEG(r, d), 1.f));
        int2 ev = { s * 32, __float_as_int(no * ni * (1.f / 3.f)) };
        g_edge[(size_t)r * EE + pos] = ev;
    }
}

// ---------------- SpMM: warp-per-row float4 gathers, paired int4 edge loads ----------------
__global__ __launch_bounds__(256) void k_spmm(const float4* __restrict__ h4,
                                              uint2* __restrict__ aggh,
                                              uint2* __restrict__ aggl) {
    int r = blockIdx.y;
    int row = blockIdx.x * 8 + (threadIdx.x >> 5);
    int lane = threadIdx.x & 31;
    if (row >= NN) return;
    int beg = g_rowptr[r * RPS + row];
    int end = g_rowptr[r * RPS + row + 1];
    if (row == NN - 1) end = g_rowptr[r * RPS + NN];
    const int2* ed = &g_edge[(size_t)r * EE];
    const int4* ed4 = reinterpret_cast<const int4*>(ed);
    float4 acc = {0.f, 0.f, 0.f, 0.f};
    int e = beg;
    // align to even edge index for int4-paired loads
    if ((e & 1) && e < end) {
        int2 ev = __ldg(&ed[e]);
        float c = __int_as_float(ev.y);
        float4 v = __ldg(&h4[ev.x + lane]);
        acc.x += c * v.x; acc.y += c * v.y; acc.z += c * v.z; acc.w += c * v.w;
        e++;
    }
    for (; e + 8 <= end; e += 8) {
        int4 p[4]; float4 v[8];
        #pragma unroll
        for (int j = 0; j < 4; j++) p[j] = __ldg(&ed4[(e >> 1) + j]);
        #pragma unroll
        for (int j = 0; j < 4; j++) {
            v[2 * j]     = __ldg(&h4[p[j].x + lane]);
            v[2 * j + 1] = __ldg(&h4[p[j].z + lane]);
        }
        #pragma unroll
        for (int j = 0; j < 4; j++) {
            float c0 = __int_as_float(p[j].y);
            float c1 = __int_as_float(p[j].w);
            acc.x += c0 * v[2 * j].x + c1 * v[2 * j + 1].x;
            acc.y += c0 * v[2 * j].y + c1 * v[2 * j + 1].y;
            acc.z += c0 * v[2 * j].z + c1 * v[2 * j + 1].z;
            acc.w += c0 * v[2 * j].w + c1 * v[2 * j + 1].w;
        }
    }
    if (e + 4 <= end) {
        int4 p[2]; float4 v[4];
        #pragma unroll
        for (int j = 0; j < 2; j++) p[j] = __ldg(&ed4[(e >> 1) + j]);
        #pragma unroll
        for (int j = 0; j < 2; j++) {
            v[2 * j]     = __ldg(&h4[p[j].x + lane]);
            v[2 * j + 1] = __ldg(&h4[p[j].z + lane]);
        }
        #pragma unroll
        for (int j = 0; j < 2; j++) {
            float c0 = __int_as_float(p[j].y);
            float c1 = __int_as_float(p[j].w);
            acc.x += c0 * v[2 * j].x + c1 * v[2 * j + 1].x;
            acc.y += c0 * v[2 * j].y + c1 * v[2 * j + 1].y;
            acc.z += c0 * v[2 * j].z + c1 * v[2 * j + 1].z;
            acc.w += c0 * v[2 * j].w + c1 * v[2 * j + 1].w;
        }
        e += 4;
    }
    for (; e < end; e++) {
        int2 ev = __ldg(&ed[e]);
        float c = __int_as_float(ev.y);
        float4 v = __ldg(&h4[ev.x + lane]);
        acc.x += c * v.x; acc.y += c * v.y; acc.z += c * v.z; acc.w += c * v.w;
    }
    __nv_bfloat162 h01(__float2bfloat16(acc.x), __float2bfloat16(acc.y));
    __nv_bfloat162 h23(__float2bfloat16(acc.z), __float2bfloat16(acc.w));
    __nv_bfloat162 l01(__float2bfloat16(acc.x - __bfloat162float(h01.x)),
                       __float2bfloat16(acc.y - __bfloat162float(h01.y)));
    __nv_bfloat162 l23(__float2bfloat16(acc.z - __bfloat162float(h23.x)),
                       __float2bfloat16(acc.w - __bfloat162float(h23.y)));
    size_t idx = ((size_t)r * NP + row) * 32 + lane;
    uint2 hv = { *reinterpret_cast<uint32_t*>(&h01), *reinterpret_cast<uint32_t*>(&h23) };
    uint2 lv = { *reinterpret_cast<uint32_t*>(&l01), *reinterpret_cast<uint32_t*>(&l23) };
    aggh[idx] = hv;
    aggl[idx] = lv;
}

// ---------------- weight prep: hidden layers 0..3 fp32 -> bf16 hi/lo + folded biases ----------------
__global__ void k_wprep(const float* __restrict__ W0, const float* __restrict__ Wl,
                        const float* __restrict__ b0, const float* __restrict__ bl) {
    int i = blockIdx.x * 256 + threadIdx.x;
    if (i < WHID) {
        float f = (i < WLAYER) ? W0[i] : Wl[i - WLAYER];
        __nv_bfloat16 h = __float2bfloat16(f);
        g_wh[i] = h;
        g_wl[i] = __float2bfloat16(f - __bfloat162float(h));
    } else if (i < WHID + 4 * FD) {
        int t = i - WHID;
        int l = t >> 7, col = t & 127;
        const float* b = (l == 0) ? b0 : (bl + (size_t)(l - 1) * RR * FD);
        g_biasm[t] = (b[col] + b[FD + col] + b[2 * FD + col]) * (1.f / 3.f);
    }
}

// ---------------- fused final layer: Wf = W4cat @ Wout, biasf = mean(b4) @ Wout + bout ----------------
__global__ void k_wfuse(const float* __restrict__ Wl, const float* __restrict__ Wout,
                        const float* __restrict__ bl, const float* __restrict__ bout) {
    int t = blockIdx.x * 256 + threadIdx.x;
    if (t < WFUSE) {
        int n = t & (OUTD - 1), m = t >> 6;
        const float* w4 = Wl + 3 * WLAYER + (size_t)m * FD;   // row m of [384][128]
        float s = 0.f;
        #pragma unroll 4
        for (int j = 0; j < FD; j++) s += w4[j] * __ldg(&Wout[(size_t)j * OUTD + n]);
        __nv_bfloat16 h = __float2bfloat16(s);
        g_wh[WHID + t] = h;
        g_wl[WHID + t] = __float2bfloat16(s - __bfloat162float(h));
    } else if (t < WFUSE + OUTD) {
        int n = t - WFUSE;
        const float* b4 = bl + 3 * RR * FD;
        float s = bout[n];
        for (int j = 0; j < FD; j++) {
            float bm = (b4[j] + b4[FD + j] + b4[2 * FD + j]) * (1.f / 3.f);
            s += bm * Wout[(size_t)j * OUTD + n];
        }
        g_biasf[n] = s;
    }
}

// ---------------- mma.sync GEMM: C[M,BN] = A[M,32*KITER] @ W, bf16 hi/lo split ----------------
// A (bf16) layout: A[((k>>7)*NP + row)*128 + (k&127)]  (relation-chunked concat)
// B (bf16) row-major [K][BN]. 512 threads, BM=128, warp grid 4x4. bias prefolded.
template <int BN, int KITER, bool RELU>
__global__ __launch_bounds__(512) void k_mgemm(const __nv_bfloat16* __restrict__ Ah,
                                               const __nv_bfloat16* __restrict__ Al,
                                               const __nv_bfloat16* __restrict__ Bh,
                                               const __nv_bfloat16* __restrict__ Bl,
                                               const float* __restrict__ bias,
                                               float* __restrict__ C, int M) {
    constexpr int APITCH = 40;                 // bf16 units (80B rows: conflict-free ldsm)
    constexpr int BPITCH = BN + 8;
    constexpr int ASZ = 128 * APITCH * 2;
    constexpr int BSZ = 32 * BPITCH * 2;
    constexpr int STG = 2 * ASZ + 2 * BSZ;
    constexpr int WN = BN / 4;
    constexpr int NT = WN / 8;
    constexpr int NSEG = BN / 8;

    extern __shared__ char smem[];
    uint32_t sb = smem_u32(smem);
    const int tid = threadIdx.x;
    const int wid = tid >> 5, lane = tid & 31;
    const int warp_row = wid >> 2, warp_col = wid & 3;
    const int blockRow = blockIdx.x * 128;

    auto load_chunk = [&](int it, int s) {
        uint32_t stg = sb + s * STG;
        int kg = it * 32;
        int rel = kg >> 7, kloc = kg & 127;
        int arow = tid >> 2, aseg = tid & 3;
        size_t abase = ((size_t)rel * NP + blockRow + arow) * 128 + kloc + aseg * 8;
        uint32_t ad = stg + (arow * APITCH + aseg * 8) * 2;
        cpasync16(ad,       Ah + abase);
        cpasync16(ad + ASZ, Al + abase);
        if (tid < 32 * NSEG) {
            int brow = tid / NSEG, bseg = tid % NSEG;
            size_t bbase = (size_t)(kg + brow) * BN + bseg * 8;
            uint32_t bd = stg + 2 * ASZ + (brow * BPITCH + bseg * 8) * 2;
            cpasync16(bd,       Bh + bbase);
            cpasync16(bd + BSZ, Bl + bbase);
        }
    };

    float acc[2][NT][4];
    #pragma unroll
    for (int mt = 0; mt < 2; mt++)
        #pragma unroll
        for (int nt = 0; nt < NT; nt++)
            #pragma unroll
            for (int j = 0; j < 4; j++) acc[mt][nt][j] = 0.f;

    load_chunk(0, 0);
    cp_commit();

    #pragma unroll 1
    for (int it = 0; it < KITER; it++) {
        if (it + 1 < KITER) {
            load_chunk(it + 1, (it + 1) & 1);
            cp_commit();
            cp_wait<1>();
        } else {
            cp_wait<0>();
        }
        __syncthreads();
        uint32_t sA  = sb + (it & 1) * STG;
        uint32_t sB  = sA + 2 * ASZ;
        #pragma unroll
        for (int ks = 0; ks < 2; ks++) {
            uint32_t ah[2][4], al_[2][4];
            #pragma unroll
            for (int mt = 0; mt < 2; mt++) {
                uint32_t ad = sA + ((warp_row * 32 + mt * 16 + (lane & 15)) * APITCH +
                                    ks * 16 + (lane >> 4) * 8) * 2;
                ldsm_x4(ah[mt], ad);
                ldsm_x4(al_[mt], ad + ASZ);
            }
            uint32_t bh[NT / 2][4], bl[NT / 2][4];
            #pragma unroll
            for (int p = 0; p < NT / 2; p++) {
                uint32_t bd = sB + ((ks * 16 + (lane & 15)) * BPITCH +
                                    warp_col * WN + p * 16 + (lane >> 4) * 8) * 2;
                ldsm_x4t(bh[p], bd);
                ldsm_x4t(bl[p], bd + BSZ);
            }
            #pragma unroll
            for (int mt = 0; mt < 2; mt++)
                #pragma unroll
                for (int nt = 0; nt < NT; nt++) {
                    const uint32_t* bhp = &bh[nt >> 1][(nt & 1) * 2];
                    const uint32_t* blp = &bl[nt >> 1][(nt & 1) * 2];
                    mma16816(acc[mt][nt], ah[mt], bhp);
                    mma16816(acc[mt][nt], ah[mt], blp);
                    mma16816(acc[mt][nt], al_[mt], bhp);
                }
        }
        __syncthreads();
    }

    // epilogue: prefolded bias + leaky-relu + store
    const int lane4 = lane >> 2, lane2 = lane & 3;
    #pragma unroll
    for (int mt = 0; mt < 2; mt++) {
        int row0 = blockRow + warp_row * 32 + mt * 16 + lane4;
        #pragma unroll
        for (int nt = 0; nt < NT; nt++) {
            int col = warp_col * WN + nt * 8 + lane2 * 2;
            float2 bb = *reinterpret_cast<const float2*>(&bias[col]);
            #pragma unroll
            for (int h = 0; h < 2; h++) {
                int row = row0 + h * 8;
                if (row < M) {
                    float v0 = acc[mt][nt][h * 2 + 0] + bb.x;
                    float v1 = acc[mt][nt][h * 2 + 1] + bb.y;
                    if (RELU) {
                        v0 = (v0 > 0.f) ? v0 : 0.01f * v0;
                        v1 = (v1 > 0.f) ? v1 : 0.01f * v1;
                    }
                    float2 v = {v0, v1};
                    *reinterpret_cast<float2*>(&C[(size_t)row * BN + col]) = v;
                }
            }
        }
    }
}

// ---------------- launch ----------------
extern "C" void kernel_launch(void* const* d_in, const int* in_sizes, int n_in,
                              void* d_out, int out_size) {
    const float* x    = (const float*)d_in[0];
    const int*   esrc = (const int*)  d_in[1];
    const int*   edst = (const int*)  d_in[2];
    const float* W0   = (const float*)d_in[3];
    const float* b0   = (const float*)d_in[4];
    const float* Wl   = (const float*)d_in[5];
    const float* bl   = (const float*)d_in[6];
    const float* Wout = (const float*)d_in[7];
    const float* bout = (const float*)d_in[8];
    float* out = (float*)d_out;

    void *p_cnt, *p_h0, *p_h1, *p_aggh, *p_aggl, *p_wh, *p_wl, *p_bm, *p_bf;
    cudaGetSymbolAddress(&p_cnt, g_cnt);
    cudaGetSymbolAddress(&p_h0, g_h0);
    cudaGetSymbolAddress(&p_h1, g_h1);
    cudaGetSymbolAddress(&p_aggh, g_aggh);
    cudaGetSymbolAddress(&p_aggl, g_aggl);
    cudaGetSymbolAddress(&p_wh, g_wh);
    cudaGetSymbolAddress(&p_wl, g_wl);
    cudaGetSymbolAddress(&p_bm, g_biasm);
    cudaGetSymbolAddress(&p_bf, g_biasf);

    cudaFuncSetAttribute(k_mgemm<128, 12, true >, cudaFuncAttributeMaxDynamicSharedMemorySize, 75776);
    cudaFuncSetAttribute(k_mgemm<64,  12, false>, cudaFuncAttributeMaxDynamicSharedMemorySize, 59392);

    cudaMemsetAsync(p_cnt, 0, sizeof(int) * 2 * RR * NN);
    k_wprep<<<(WHID + 4 * FD + 255) / 256, 256>>>(W0, Wl, b0, bl);
    k_wfuse<<<(WFUSE + OUTD + 255) / 256, 256>>>(Wl, Wout, bl, bout);

    dim3 gd((EE / 4 + 255) / 256, RR);
    k_degree<<<gd, 256>>>((const int4*)esrc, (const int4*)edst);
    dim3 gsn(NB, RR);
    k_scan1<<<gsn, 1024>>>();
    k_scan2<<<1, 32>>>();
    k_scan3<<<gsn, 1024>>>();
    dim3 ge((EE + 255) / 256, RR);
    k_fill<<<ge, 256>>>(esrc, edst);

    float4* hbuf[2] = { (float4*)p_h0, (float4*)p_h1 };
    uint2* aggh = (uint2*)p_aggh;
    uint2* aggl = (uint2*)p_aggl;
    const __nv_bfloat16* wh = (const __nv_bfloat16*)p_wh;
    const __nv_bfloat16* wl = (const __nv_bfloat16*)p_wl;
    const float* biasm = (const float*)p_bm;

    dim3 gs((NN + 7) / 8, RR);
    const int GB = (NN + 127) / 128;   // 391

    const float4* cur = (const float4*)x;
    for (int l = 0; l < 4; l++) {
        k_spmm<<<gs, 256>>>(cur, aggh, aggl);
        float* hout = (float*)hbuf[l & 1];
        k_mgemm<128, 12, true><<<GB, 512, 75776>>>(
            (const __nv_bfloat16*)aggh, (const __nv_bfloat16*)aggl,
            wh + (size_t)l * WLAYER, wl + (size_t)l * WLAYER, biasm + l * FD,
            hout, NN);
        cur = (const float4*)hout;
    }

    // layer 4 fused with final Linear: out = agg @ (W4cat @ Wout) + biasf
    k_spmm<<<gs, 256>>>(cur, aggh, aggl);
    k_mgemm<64, 12, false><<<GB, 512, 59392>>>(
        (const __nv_bfloat16*)aggh, (const __nv_bfloat16*)aggl,
        wh + WHID, wl + WHID, (const float*)p_bf,
        out, NN);
}

// round 16
// speedup vs baseline: 1.1242x; 1.1242x over previous
#include <cuda_runtime.h>
#include <cuda_bf16.h>
#include <cstdint>

#define NN   50000
#define NP   50128           // padded rows (OOB-safe cp.async for last block)
#define FD   128
#define RR   3
#define EE   800000
#define OUTD 64
#define NNFD ((size_t)NN * FD)
#define WLAYER (RR * FD * FD)          // 49152 per hidden layer
#define WHID   (4 * WLAYER)            // hidden layers 0..3
#define WFUSE  (RR * FD * OUTD)        // fused layer-4 weight [384][64]
#define WTOT   (WHID + WFUSE)
#define STILE  4096                    // scan tile (1024 thr x 4)
#define NB     ((NN + STILE - 1) / STILE)   // 13 tiles / relation
#define RPS    (NN + 4)                // rowptr row stride, multiple of 4 -> int4-aligned

// prep kernel index ranges
#define PREP_BIAS   (WHID)                 // + 4*FD folded biases
#define PREP_FUSE   (WHID + 4 * FD)        // + WFUSE fused weights
#define PREP_BIASF  (PREP_FUSE + WFUSE)    // + OUTD fused bias
#define PREP_TOT    (PREP_BIASF + OUTD)

// ---------------- static device scratch ----------------
__device__ float4 g_h0[NNFD / 4];
__device__ float4 g_h1[NNFD / 4];
__device__ uint2  g_aggh[(size_t)RR * NP * 32];   // bf16 hi image of agg [r][row][128]
__device__ uint2  g_aggl[(size_t)RR * NP * 32];   // bf16 lo image
__device__ __nv_bfloat16 g_wh[WTOT];              // weight hi ([K][N] row-major per layer)
__device__ __nv_bfloat16 g_wl[WTOT];
__device__ float  g_biasm[4 * FD];                // folded mean bias, layers 0..3
__device__ float  g_biasf[OUTD];                  // fused final bias
__device__ int    g_rowptr[RR * RPS];             // per-relation rowptr (element NN = total)
__device__ int    g_wptr[RR * NN];                // working copy for fill's slot atomics
__device__ int    g_cnt[2 * RR * NN];             // [outdeg | indeg] contiguous
__device__ int    g_bsum[RR * NB];                // per-tile sums
__device__ int    g_bpre[RR * NB];                // per-tile exclusive prefixes
__device__ int2   g_edge[(size_t)RR * EE];        // {src*32 (float4 units), coef bits}, CSR by dst

#define ODEG(r, n) g_cnt[(r) * NN + (n)]
#define IDEG(r, n) g_cnt[RR * NN + (r) * NN + (n)]

// ---------------- ptx helpers (baseline PTX only) ----------------
__device__ __forceinline__ uint32_t smem_u32(const void* p) {
    uint32_t a;
    asm("{ .reg .u64 t; cvta.to.shared.u64 t, %1; cvt.u32.u64 %0, t; }" : "=r"(a) : "l"(p));
    return a;
}
__device__ __forceinline__ void cpasync16(uint32_t sdst, const void* gsrc) {
    asm volatile("cp.async.cg.shared.global [%0], [%1], 16;" :: "r"(sdst), "l"(gsrc) : "memory");
}
__device__ __forceinline__ void cp_commit() {
    asm volatile("cp.async.commit_group;" ::: "memory");
}
template <int N>
__device__ __forceinline__ void cp_wait() {
    asm volatile("cp.async.wait_group %0;" :: "n"(N) : "memory");
}
__device__ __forceinline__ void ldsm_x4(uint32_t* r, uint32_t addr) {
    asm volatile("ldmatrix.sync.aligned.m8n8.x4.shared.b16 {%0,%1,%2,%3}, [%4];"
                 : "=r"(r[0]), "=r"(r[1]), "=r"(r[2]), "=r"(r[3]) : "r"(addr));
}
__device__ __forceinline__ void ldsm_x4t(uint32_t* r, uint32_t addr) {
    asm volatile("ldmatrix.sync.aligned.m8n8.x4.trans.shared.b16 {%0,%1,%2,%3}, [%4];"
                 : "=r"(r[0]), "=r"(r[1]), "=r"(r[2]), "=r"(r[3]) : "r"(addr));
}
__device__ __forceinline__ void mma16816(float* d, const uint32_t* a, const uint32_t* b) {
    asm volatile("mma.sync.aligned.m16n8k16.row.col.f32.bf16.bf16.f32 "
                 "{%0,%1,%2,%3},{%4,%5,%6,%7},{%8,%9},{%0,%1,%2,%3};"
                 : "+f"(d[0]), "+f"(d[1]), "+f"(d[2]), "+f"(d[3])
                 : "r"(a[0]), "r"(a[1]), "r"(a[2]), "r"(a[3]), "r"(b[0]), "r"(b[1]));
}

// ---------------- degree histogram (4 edges / thread, int4 loads) ----------------
__global__ void k_degree(const int4* __restrict__ src4, const int4* __restrict__ dst4) {
    int i = blockIdx.x * blockDim.x + threadIdx.x;
    int r = blockIdx.y;
    if (i < EE / 4) {
        int4 s = __ldg(&src4[(size_t)r * (EE / 4) + i]);
        int4 d = __ldg(&dst4[(size_t)r * (EE / 4) + i]);
        atomicAdd(&ODEG(r, s.x), 1); atomicAdd(&ODEG(r, s.y), 1);
        atomicAdd(&ODEG(r, s.z), 1); atomicAdd(&ODEG(r, s.w), 1);
        atomicAdd(&IDEG(r, d.x), 1); atomicAdd(&IDEG(r, d.y), 1);
        atomicAdd(&IDEG(r, d.z), 1); atomicAdd(&IDEG(r, d.w), 1);
    }
}

// ---------------- scan phase 1: per-tile sums (coalesced int4) ----------------
__global__ __launch_bounds__(1024) void k_scan1() {
    int r = blockIdx.y, b = blockIdx.x, t = threadIdx.x;
    int lane = t & 31, wid = t >> 5;
    __shared__ int wsum[32];
    int base = b * STILE + t * 4;
    int s = 0;
    if (base + 3 < NN) {
        int4 v = *(const int4*)&IDEG(r, base);
        s = v.x + v.y + v.z + v.w;
    } else {
        #pragma unroll
        for (int j = 0; j < 4; j++)
            if (base + j < NN) s += IDEG(r, base + j);
    }
    #pragma unroll
    for (int d = 16; d > 0; d >>= 1) s += __shfl_down_sync(0xffffffffu, s, d);
    if (lane == 0) wsum[wid] = s;
    __syncthreads();
    if (wid == 0) {
        s = wsum[lane];
        #pragma unroll
        for (int d = 16; d > 0; d >>= 1) s += __shfl_down_sync(0xffffffffu, s, d);
        if (lane == 0) g_bsum[r * NB + b] = s;
    }
}

// ---------------- scan phase 2: scan the 13 tile sums per relation ----------------
__global__ void k_scan2() {
    int r = threadIdx.x;
    if (r < RR) {
        int pre = 0;
        #pragma unroll
        for (int i = 0; i < NB; i++) {
            int v = g_bsum[r * NB + i];
            g_bpre[r * NB + i] = pre;
            pre += v;
        }
        g_rowptr[r * RPS + NN] = pre;
    }
}

// ---------------- scan phase 3: block-local exclusive scan + tile offset ----------------
__global__ __launch_bounds__(1024) void k_scan3() {
    int r = blockIdx.y, b = blockIdx.x, t = threadIdx.x;
    int lane = t & 31, wid = t >> 5;
    __shared__ int wsum[32];
    int base = b * STILE + t * 4;
    int v0 = 0, v1 = 0, v2 = 0, v3 = 0;
    if (base + 3 < NN) {
        int4 v = *(const int4*)&IDEG(r, base);
        v0 = v.x; v1 = v.y; v2 = v.z; v3 = v.w;
    } else {
        if (base + 0 < NN) v0 = IDEG(r, base + 0);
        if (base + 1 < NN) v1 = IDEG(r, base + 1);
        if (base + 2 < NN) v2 = IDEG(r, base + 2);
        if (base + 3 < NN) v3 = IDEG(r, base + 3);
    }
    int ts = v0 + v1 + v2 + v3;
    int incl = ts;
    #pragma unroll
    for (int d = 1; d < 32; d <<= 1) {
        int u = __shfl_up_sync(0xffffffffu, incl, d);
        if (lane >= d) incl += u;
    }
    if (lane == 31) wsum[wid] = incl;
    __syncthreads();
    if (wid == 0) {
        int w = wsum[lane];
        int wi = w;
        #pragma unroll
        for (int d = 1; d < 32; d <<= 1) {
            int u = __shfl_up_sync(0xffffffffu, wi, d);
            if (lane >= d) wi += u;
        }
        wsum[lane] = wi - w;
    }
    __syncthreads();
    int pre = g_bpre[r * NB + b] + wsum[wid] + incl - ts;
    int p0 = pre, p1 = p0 + v0, p2 = p1 + v1, p3 = p2 + v2;
    if (base + 3 < NN) {
        int4 pv = {p0, p1, p2, p3};
        *(int4*)&g_rowptr[r * RPS + base] = pv;
        *(int4*)&g_wptr[r * NN + base] = pv;
    } else {
        int pp[4] = {p0, p1, p2, p3};
        #pragma unroll
        for (int j = 0; j < 4; j++)
            if (base + j < NN) {
                g_rowptr[r * RPS + base + j] = pp[j];
                g_wptr[r * NN + base + j] = pp[j];
            }
    }
}

// ---------------- counting-sort fill: direct slot atomic + single int2 store ----------------
__global__ void k_fill(const int* __restrict__ src, const int* __restrict__ dst) {
    int e = blockIdx.x * blockDim.x + threadIdx.x;
    int r = blockIdx.y;
    if (e < EE) {
        int s = src[(size_t)r * EE + e];
        int d = dst[(size_t)r * EE + e];
        int pos = atomicAdd(&g_wptr[r * NN + d], 1);
        float no = rsqrtf(fmaxf((float)ODEG(r, s), 1.f));
        float ni = rsqrtf(fmaxf((float)IDEG(r, d), 1.f));
        int2 ev = { s * 32, __float_as_int(no * ni * (1.f / 3.f)) };
        g_edge[(size_t)r * EE + pos] = ev;
    }
}

// ---------------- SpMM (round-13 proven form): warp-per-row float4 gathers, MLP=8 ----------------
__global__ __launch_bounds__(256) void k_spmm(const float4* __restrict__ h4,
                                              uint2* __restrict__ aggh,
                                              uint2* __restrict__ aggl) {
    int r = blockIdx.y;
    int row = blockIdx.x * 8 + (threadIdx.x >> 5);
    int lane = threadIdx.x & 31;
    if (row >= NN) return;
    int beg = g_rowptr[r * RPS + row];
    int end = g_rowptr[r * RPS + row + 1];
    if (row == NN - 1) end = g_rowptr[r * RPS + NN];
    const int2* ed = &g_edge[(size_t)r * EE];
    float4 acc = {0.f, 0.f, 0.f, 0.f};
    int e = beg;
    for (; e + 8 <= end; e += 8) {
        int2 ev[8]; float4 v[8];
        #pragma unroll
        for (int j = 0; j < 8; j++) ev[j] = __ldg(&ed[e + j]);
        #pragma unroll
        for (int j = 0; j < 8; j++) v[j] = __ldg(&h4[ev[j].x + lane]);
        #pragma unroll
        for (int j = 0; j < 8; j++) {
            float c = __int_as_float(ev[j].y);
            acc.x += c * v[j].x;
            acc.y += c * v[j].y;
            acc.z += c * v[j].z;
            acc.w += c * v[j].w;
        }
    }
    if (e + 4 <= end) {
        int2 ev[4]; float4 v[4];
        #pragma unroll
        for (int j = 0; j < 4; j++) ev[j] = __ldg(&ed[e + j]);
        #pragma unroll
        for (int j = 0; j < 4; j++) v[j] = __ldg(&h4[ev[j].x + lane]);
        #pragma unroll
        for (int j = 0; j < 4; j++) {
            float c = __int_as_float(ev[j].y);
            acc.x += c * v[j].x;
            acc.y += c * v[j].y;
            acc.z += c * v[j].z;
            acc.w += c * v[j].w;
        }
        e += 4;
    }
    for (; e < end; e++) {
        int2 ev = __ldg(&ed[e]);
        float c = __int_as_float(ev.y);
        float4 v = __ldg(&h4[ev.x + lane]);
        acc.x += c * v.x; acc.y += c * v.y; acc.z += c * v.z; acc.w += c * v.w;
    }
    __nv_bfloat162 h01(__float2bfloat16(acc.x), __float2bfloat16(acc.y));
    __nv_bfloat162 h23(__float2bfloat16(acc.z), __float2bfloat16(acc.w));
    __nv_bfloat162 l01(__float2bfloat16(acc.x - __bfloat162float(h01.x)),
                       __float2bfloat16(acc.y - __bfloat162float(h01.y)));
    __nv_bfloat162 l23(__float2bfloat16(acc.z - __bfloat162float(h23.x)),
                       __float2bfloat16(acc.w - __bfloat162float(h23.y)));
    size_t idx = ((size_t)r * NP + row) * 32 + lane;
    uint2 hv = { *reinterpret_cast<uint32_t*>(&h01), *reinterpret_cast<uint32_t*>(&h23) };
    uint2 lv = { *reinterpret_cast<uint32_t*>(&l01), *reinterpret_cast<uint32_t*>(&l23) };
    aggh[idx] = hv;
    aggl[idx] = lv;
}

// ---------------- single prep kernel: weight split + bias fold + final-layer fusion ----------------
__global__ void k_prep(const float* __restrict__ W0, const float* __restrict__ Wl,
                       const float* __restrict__ Wout,
                       const float* __restrict__ b0, const float* __restrict__ bl,
                       const float* __restrict__ bout) {
    int i = blockIdx.x * 256 + threadIdx.x;
    if (i < PREP_BIAS) {
        // hidden-layer weight split
        float f = (i < WLAYER) ? W0[i] : Wl[i - WLAYER];
        __nv_bfloat16 h = __float2bfloat16(f);
        g_wh[i] = h;
        g_wl[i] = __float2bfloat16(f - __bfloat162float(h));
    } else if (i < PREP_FUSE) {
        // folded mean bias for layers 0..3
        int t = i - PREP_BIAS;
        int l = t >> 7, col = t & 127;
        const float* b = (l == 0) ? b0 : (bl + (size_t)(l - 1) * RR * FD);
        g_biasm[t] = (b[col] + b[FD + col] + b[2 * FD + col]) * (1.f / 3.f);
    } else if (i < PREP_BIASF) {
        // fused final weight: Wf[m][n] = sum_j W4cat[m][j] * Wout[j][n]
        int t = i - PREP_FUSE;
        int n = t & (OUTD - 1), m = t >> 6;
        const float* w4 = Wl + 3 * WLAYER + (size_t)m * FD;
        float s = 0.f;
        #pragma unroll 4
        for (int j = 0; j < FD; j++) s += w4[j] * __ldg(&Wout[(size_t)j * OUTD + n]);
        __nv_bfloat16 h = __float2bfloat16(s);
        g_wh[WHID + t] = h;
        g_wl[WHID + t] = __float2bfloat16(s - __bfloat162float(h));
    } else if (i < PREP_TOT) {
        // fused final bias
        int n = i - PREP_BIASF;
        const float* b4 = bl + 3 * RR * FD;
        float s = bout[n];
        for (int j = 0; j < FD; j++) {
            float bm = (b4[j] + b4[FD + j] + b4[2 * FD + j]) * (1.f / 3.f);
            s += bm * Wout[(size_t)j * OUTD + n];
        }
        g_biasf[n] = s;
    }
}

// ---------------- mma.sync GEMM: C[M,BN] = A[M,32*KITER] @ W, bf16 hi/lo split ----------------
// A (bf16) layout: A[((k>>7)*NP + row)*128 + (k&127)]  (relation-chunked concat)
// B (bf16) row-major [K][BN]. 512 threads, BM=128, warp grid 4x4. bias prefolded.
template <int BN, int KITER, bool RELU>
__global__ __launch_bounds__(512) void k_mgemm(const __nv_bfloat16* __restrict__ Ah,
                                               const __nv_bfloat16* __restrict__ Al,
                                               const __nv_bfloat16* __restrict__ Bh,
                                               const __nv_bfloat16* __restrict__ Bl,
                                               const float* __restrict__ bias,
                                               float* __restrict__ C, int M) {
    constexpr int APITCH = 40;                 // bf16 units (80B rows: conflict-free ldsm)
    constexpr int BPITCH = BN + 8;
    constexpr int ASZ = 128 * APITCH * 2;
    constexpr int BSZ = 32 * BPITCH * 2;
    constexpr int STG = 2 * ASZ + 2 * BSZ;
    constexpr int WN = BN / 4;
    constexpr int NT = WN / 8;
    constexpr int NSEG = BN / 8;

    extern __shared__ char smem[];
    uint32_t sb = smem_u32(smem);
    const int tid = threadIdx.x;
    const int wid = tid >> 5, lane = tid & 31;
    const int warp_row = wid >> 2, warp_col = wid & 3;
    const int blockRow = blockIdx.x * 128;

    auto load_chunk = [&](int it, int s) {
        uint32_t stg = sb + s * STG;
        int kg = it * 32;
        int rel = kg >> 7, kloc = kg & 127;
        int arow = tid >> 2, aseg = tid & 3;
        size_t abase = ((size_t)rel * NP + blockRow + arow) * 128 + kloc + aseg * 8;
        uint32_t ad = stg + (arow * APITCH + aseg * 8) * 2;
        cpasync16(ad,       Ah + abase);
        cpasync16(ad + ASZ, Al + abase);
        if (tid < 32 * NSEG) {
            int brow = tid / NSEG, bseg = tid % NSEG;
            size_t bbase = (size_t)(kg + brow) * BN + bseg * 8;
            uint32_t bd = stg + 2 * ASZ + (brow * BPITCH + bseg * 8) * 2;
            cpasync16(bd,       Bh + bbase);
            cpasync16(bd + BSZ, Bl + bbase);
        }
    };

    float acc[2][NT][4];
    #pragma unroll
    for (int mt = 0; mt < 2; mt++)
        #pragma unroll
        for (int nt = 0; nt < NT; nt++)
            #pragma unroll
            for (int j = 0; j < 4; j++) acc[mt][nt][j] = 0.f;

    load_chunk(0, 0);
    cp_commit();

    #pragma unroll 1
    for (int it = 0; it < KITER; it++) {
        if (it + 1 < KITER) {
            load_chunk(it + 1, (it + 1) & 1);
            cp_commit();
            cp_wait<1>();
        } else {
            cp_wait<0>();
        }
        __syncthreads();
        uint32_t sA  = sb + (it & 1) * STG;
        uint32_t sB  = sA + 2 * ASZ;
        #pragma unroll
        for (int ks = 0; ks < 2; ks++) {
            uint32_t ah[2][4], al_[2][4];
            #pragma unroll
            for (int mt = 0; mt < 2; mt++) {
                uint32_t ad = sA + ((warp_row * 32 + mt * 16 + (lane & 15)) * APITCH +
                                    ks * 16 + (lane >> 4) * 8) * 2;
                ldsm_x4(ah[mt], ad);
                ldsm_x4(al_[mt], ad + ASZ);
            }
            uint32_t bh[NT / 2][4], bl[NT / 2][4];
            #pragma unroll
            for (int p = 0; p < NT / 2; p++) {
                uint32_t bd = sB + ((ks * 16 + (lane & 15)) * BPITCH +
                                    warp_col * WN + p * 16 + (lane >> 4) * 8) * 2;
                ldsm_x4t(bh[p], bd);
                ldsm_x4t(bl[p], bd + BSZ);
            }
            #pragma unroll
            for (int mt = 0; mt < 2; mt++)
                #pragma unroll
                for (int nt = 0; nt < NT; nt++) {
                    const uint32_t* bhp = &bh[nt >> 1][(nt & 1) * 2];
                    const uint32_t* blp = &bl[nt >> 1][(nt & 1) * 2];
                    mma16816(acc[mt][nt], ah[mt], bhp);
                    mma16816(acc[mt][nt], ah[mt], blp);
                    mma16816(acc[mt][nt], al_[mt], bhp);
                }
        }
        __syncthreads();
    }

    // epilogue: prefolded bias + leaky-relu + store
    const int lane4 = lane >> 2, lane2 = lane & 3;
    #pragma unroll
    for (int mt = 0; mt < 2; mt++) {
        int row0 = blockRow + warp_row * 32 + mt * 16 + lane4;
        #pragma unroll
        for (int nt = 0; nt < NT; nt++) {
            int col = warp_col * WN + nt * 8 + lane2 * 2;
            float2 bb = *reinterpret_cast<const float2*>(&bias[col]);
            #pragma unroll
            for (int h = 0; h < 2; h++) {
                int row = row0 + h * 8;
                if (row < M) {
                    float v0 = acc[mt][nt][h * 2 + 0] + bb.x;
                    float v1 = acc[mt][nt][h * 2 + 1] + bb.y;
                    if (RELU) {
                        v0 = (v0 > 0.f) ? v0 : 0.01f * v0;
                        v1 = (v1 > 0.f) ? v1 : 0.01f * v1;
                    }
                    float2 v = {v0, v1};
                    *reinterpret_cast<float2*>(&C[(size_t)row * BN + col]) = v;
                }
            }
        }
    }
}

// ---------------- launch ----------------
extern "C" void kernel_launch(void* const* d_in, const int* in_sizes, int n_in,
                              void* d_out, int out_size) {
    const float* x    = (const float*)d_in[0];
    const int*   esrc = (const int*)  d_in[1];
    const int*   edst = (const int*)  d_in[2];
    const float* W0   = (const float*)d_in[3];
    const float* b0   = (const float*)d_in[4];
    const float* Wl   = (const float*)d_in[5];
    const float* bl   = (const float*)d_in[6];
    const float* Wout = (const float*)d_in[7];
    const float* bout = (const float*)d_in[8];
    float* out = (float*)d_out;

    void *p_cnt, *p_h0, *p_h1, *p_aggh, *p_aggl, *p_wh, *p_wl, *p_bm, *p_bf;
    cudaGetSymbolAddress(&p_cnt, g_cnt);
    cudaGetSymbolAddress(&p_h0, g_h0);
    cudaGetSymbolAddress(&p_h1, g_h1);
    cudaGetSymbolAddress(&p_aggh, g_aggh);
    cudaGetSymbolAddress(&p_aggl, g_aggl);
    cudaGetSymbolAddress(&p_wh, g_wh);
    cudaGetSymbolAddress(&p_wl, g_wl);
    cudaGetSymbolAddress(&p_bm, g_biasm);
    cudaGetSymbolAddress(&p_bf, g_biasf);

    cudaFuncSetAttribute(k_mgemm<128, 12, true >, cudaFuncAttributeMaxDynamicSharedMemorySize, 75776);
    cudaFuncSetAttribute(k_mgemm<64,  12, false>, cudaFuncAttributeMaxDynamicSharedMemorySize, 59392);

    cudaMemsetAsync(p_cnt, 0, sizeof(int) * 2 * RR * NN);
    k_prep<<<(PREP_TOT + 255) / 256, 256>>>(W0, Wl, Wout, b0, bl, bout);

    dim3 gd((EE / 4 + 255) / 256, RR);
    k_degree<<<gd, 256>>>((const int4*)esrc, (const int4*)edst);
    dim3 gsn(NB, RR);
    k_scan1<<<gsn, 1024>>>();
    k_scan2<<<1, 32>>>();
    k_scan3<<<gsn, 1024>>>();
    dim3 ge((EE + 255) / 256, RR);
    k_fill<<<ge, 256>>>(esrc, edst);

    float4* hbuf[2] = { (float4*)p_h0, (float4*)p_h1 };
    uint2* aggh = (uint2*)p_aggh;
    uint2* aggl = (uint2*)p_aggl;
    const __nv_bfloat16* wh = (const __nv_bfloat16*)p_wh;
    const __nv_bfloat16* wl = (const __nv_bfloat16*)p_wl;
    const float* biasm = (const float*)p_bm;

    dim3 gs((NN + 7) / 8, RR);
    const int GB = (NN + 127) / 128;   // 391

    const float4* cur = (const float4*)x;
    for (int l = 0; l < 4; l++) {
        k_spmm<<<gs, 256>>>(cur, aggh, aggl);
        float* hout = (float*)hbuf[l & 1];
        k_mgemm<128, 12, true><<<GB, 512, 75776>>>(
            (const __nv_bfloat16*)aggh, (const __nv_bfloat16*)aggl,
            wh + (size_t)l * WLAYER, wl + (size_t)l * WLAYER, biasm + l * FD,
            hout, NN);
        cur = (const float4*)hout;
    }

    // layer 4 fused with final Linear: out = agg @ (W4cat @ Wout) + biasf
    k_spmm<<<gs, 256>>>(cur, aggh, aggl);
    k_mgemm<64, 12, false><<<GB, 512, 59392>>>(
        (const __nv_bfloat16*)aggh, (const __nv_bfloat16*)aggl,
        wh + WHID, wl + WHID, (const float*)p_bf,
        out, NN);
}

// round 17
// speedup vs baseline: 1.1334x; 1.0082x over previous
#include <cuda_runtime.h>
#include <cuda_bf16.h>
#include <cstdint>

#define NN   50000
#define NP   50128           // padded rows (OOB-safe cp.async for last block)
#define FD   128
#define RR   3
#define EE   800000
#define OUTD 64
#define NNFD ((size_t)NN * FD)
#define WLAYER (RR * FD * FD)          // 49152 per hidden layer
#define WHID   (4 * WLAYER)            // hidden layers 0..3
#define WFUSE  (RR * FD * OUTD)        // fused layer-4 weight [384][64]
#define WTOT   (WHID + WFUSE)
#define STILE  4096                    // scan tile (1024 thr x 4)
#define NB     ((NN + STILE - 1) / STILE)   // 13 tiles / relation
#define RPS    (NN + 4)                // rowptr row stride, multiple of 4 -> int4-aligned

// prep kernel index ranges
#define PREP_BIAS   (WHID)                 // + 4*FD folded biases
#define PREP_FUSE   (WHID + 4 * FD)        // + WFUSE fused weights
#define PREP_BIASF  (PREP_FUSE + WFUSE)    // + OUTD fused bias
#define PREP_ZERO   (PREP_BIASF + OUTD)    // + 2*RR*NN/4 int4 zeros of g_cnt
#define NZERO4      (2 * RR * NN / 4)      // 75000
#define PREP_TOT    (PREP_ZERO + NZERO4)

// ---------------- static device scratch ----------------
__device__ float4 g_h0[NNFD / 4];
__device__ float4 g_h1[NNFD / 4];
__device__ uint2  g_aggh[(size_t)RR * NP * 32];   // bf16 hi image of agg [r][row][128]
__device__ uint2  g_aggl[(size_t)RR * NP * 32];   // bf16 lo image
__device__ __nv_bfloat16 g_wh[WTOT];              // weight hi ([K][N] row-major per layer)
__device__ __nv_bfloat16 g_wl[WTOT];
__device__ float  g_biasm[4 * FD];                // folded mean bias, layers 0..3
__device__ float  g_biasf[OUTD];                  // fused final bias
__device__ int    g_rowptr[RR * RPS];             // per-relation rowptr (element NN = total)
__device__ int    g_wptr[RR * NN];                // working copy for fill's slot atomics
__device__ int    g_cnt[2 * RR * NN];             // [outdeg | indeg] contiguous (int4-aligned)
__device__ int    g_bsum[RR * NB];                // per-tile sums
__device__ int2   g_edge[(size_t)RR * EE];        // {src*32 (float4 units), coef bits}, CSR by dst

#define ODEG(r, n) g_cnt[(r) * NN + (n)]
#define IDEG(r, n) g_cnt[RR * NN + (r) * NN + (n)]

// ---------------- ptx helpers (baseline PTX only) ----------------
__device__ __forceinline__ uint32_t smem_u32(const void* p) {
    uint32_t a;
    asm("{ .reg .u64 t; cvta.to.shared.u64 t, %1; cvt.u32.u64 %0, t; }" : "=r"(a) : "l"(p));
    return a;
}
__device__ __forceinline__ void cpasync16(uint32_t sdst, const void* gsrc) {
    asm volatile("cp.async.cg.shared.global [%0], [%1], 16;" :: "r"(sdst), "l"(gsrc) : "memory");
}
__device__ __forceinline__ void cp_commit() {
    asm volatile("cp.async.commit_group;" ::: "memory");
}
template <int N>
__device__ __forceinline__ void cp_wait() {
    asm volatile("cp.async.wait_group %0;" :: "n"(N) : "memory");
}
__device__ __forceinline__ void ldsm_x4(uint32_t* r, uint32_t addr) {
    asm volatile("ldmatrix.sync.aligned.m8n8.x4.shared.b16 {%0,%1,%2,%3}, [%4];"
                 : "=r"(r[0]), "=r"(r[1]), "=r"(r[2]), "=r"(r[3]) : "r"(addr));
}
__device__ __forceinline__ void ldsm_x4t(uint32_t* r, uint32_t addr) {
    asm volatile("ldmatrix.sync.aligned.m8n8.x4.trans.shared.b16 {%0,%1,%2,%3}, [%4];"
                 : "=r"(r[0]), "=r"(r[1]), "=r"(r[2]), "=r"(r[3]) : "r"(addr));
}
__device__ __forceinline__ void mma16816(float* d, const uint32_t* a, const uint32_t* b) {
    asm volatile("mma.sync.aligned.m16n8k16.row.col.f32.bf16.bf16.f32 "
                 "{%0,%1,%2,%3},{%4,%5,%6,%7},{%8,%9},{%0,%1,%2,%3};"
                 : "+f"(d[0]), "+f"(d[1]), "+f"(d[2]), "+f"(d[3])
                 : "r"(a[0]), "r"(a[1]), "r"(a[2]), "r"(a[3]), "r"(b[0]), "r"(b[1]));
}

// ---------------- single prep kernel: weight split + bias fold + fusion + counter zero ----------------
__global__ void k_prep(const float* __restrict__ W0, const float* __restrict__ Wl,
                       const float* __restrict__ Wout,
                       const float* __restrict__ b0, const float* __restrict__ bl,
                       const float* __restrict__ bout) {
    int i = blockIdx.x * 256 + threadIdx.x;
    if (i < PREP_BIAS) {
        float f = (i < WLAYER) ? W0[i] : Wl[i - WLAYER];
        __nv_bfloat16 h = __float2bfloat16(f);
        g_wh[i] = h;
        g_wl[i] = __float2bfloat16(f - __bfloat162float(h));
    } else if (i < PREP_FUSE) {
        int t = i - PREP_BIAS;
        int l = t >> 7, col = t & 127;
        const float* b = (l == 0) ? b0 : (bl + (size_t)(l - 1) * RR * FD);
        g_biasm[t] = (b[col] + b[FD + col] + b[2 * FD + col]) * (1.f / 3.f);
    } else if (i < PREP_BIASF) {
        int t = i - PREP_FUSE;
        int n = t & (OUTD - 1), m = t >> 6;
        const float* w4 = Wl + 3 * WLAYER + (size_t)m * FD;
        float s = 0.f;
        #pragma unroll 4
        for (int j = 0; j < FD; j++) s += w4[j] * __ldg(&Wout[(size_t)j * OUTD + n]);
        __nv_bfloat16 h = __float2bfloat16(s);
        g_wh[WHID + t] = h;
        g_wl[WHID + t] = __float2bfloat16(s - __bfloat162float(h));
    } else if (i < PREP_ZERO) {
        int n = i - PREP_BIASF;
        const float* b4 = bl + 3 * RR * FD;
        float s = bout[n];
        for (int j = 0; j < FD; j++) {
            float bm = (b4[j] + b4[FD + j] + b4[2 * FD + j]) * (1.f / 3.f);
            s += bm * Wout[(size_t)j * OUTD + n];
        }
        g_biasf[n] = s;
    } else if (i < PREP_TOT) {
        int t = i - PREP_ZERO;
        int4 z = {0, 0, 0, 0};
        *(int4*)&g_cnt[t * 4] = z;
    }
}

// ---------------- degree histogram (4 edges / thread, int4 loads) ----------------
__global__ void k_degree(const int4* __restrict__ src4, const int4* __restrict__ dst4) {
    int i = blockIdx.x * blockDim.x + threadIdx.x;
    int r = blockIdx.y;
    if (i < EE / 4) {
        int4 s = __ldg(&src4[(size_t)r * (EE / 4) + i]);
        int4 d = __ldg(&dst4[(size_t)r * (EE / 4) + i]);
        atomicAdd(&ODEG(r, s.x), 1); atomicAdd(&ODEG(r, s.y), 1);
        atomicAdd(&ODEG(r, s.z), 1); atomicAdd(&ODEG(r, s.w), 1);
        atomicAdd(&IDEG(r, d.x), 1); atomicAdd(&IDEG(r, d.y), 1);
        atomicAdd(&IDEG(r, d.z), 1); atomicAdd(&IDEG(r, d.w), 1);
    }
}

// ---------------- scan phase 1: per-tile sums (coalesced int4) ----------------
__global__ __launch_bounds__(1024) void k_scan1() {
    int r = blockIdx.y, b = blockIdx.x, t = threadIdx.x;
    int lane = t & 31, wid = t >> 5;
    __shared__ int wsum[32];
    int base = b * STILE + t * 4;
    int s = 0;
    if (base + 3 < NN) {
        int4 v = *(const int4*)&IDEG(r, base);
        s = v.x + v.y + v.z + v.w;
    } else {
        #pragma unroll
        for (int j = 0; j < 4; j++)
            if (base + j < NN) s += IDEG(r, base + j);
    }
    #pragma unroll
    for (int d = 16; d > 0; d >>= 1) s += __shfl_down_sync(0xffffffffu, s, d);
    if (lane == 0) wsum[wid] = s;
    __syncthreads();
    if (wid == 0) {
        s = wsum[lane];
        #pragma unroll
        for (int d = 16; d > 0; d >>= 1) s += __shfl_down_sync(0xffffffffu, s, d);
        if (lane == 0) g_bsum[r * NB + b] = s;
    }
}

// ---------------- scan phase 2: block-local exclusive scan; tile prefix computed in-block ----------------
__global__ __launch_bounds__(1024) void k_scan3() {
    int r = blockIdx.y, b = blockIdx.x, t = threadIdx.x;
    int lane = t & 31, wid = t >> 5;
    __shared__ int wsum[32];
    // per-tile exclusive prefix (NB=13 values, computed redundantly per thread)
    int tilepre = 0, tiletot = 0;
    #pragma unroll
    for (int i = 0; i < NB; i++) {
        int v = __ldg(&g_bsum[r * NB + i]);
        if (i < b) tilepre += v;
        tiletot += v;
    }
    int base = b * STILE + t * 4;
    int v0 = 0, v1 = 0, v2 = 0, v3 = 0;
    if (base + 3 < NN) {
        int4 v = *(const int4*)&IDEG(r, base);
        v0 = v.x; v1 = v.y; v2 = v.z; v3 = v.w;
    } else {
        if (base + 0 < NN) v0 = IDEG(r, base + 0);
        if (base + 1 < NN) v1 = IDEG(r, base + 1);
        if (base + 2 < NN) v2 = IDEG(r, base + 2);
        if (base + 3 < NN) v3 = IDEG(r, base + 3);
    }
    int ts = v0 + v1 + v2 + v3;
    int incl = ts;
    #pragma unroll
    for (int d = 1; d < 32; d <<= 1) {
        int u = __shfl_up_sync(0xffffffffu, incl, d);
        if (lane >= d) incl += u;
    }
    if (lane == 31) wsum[wid] = incl;
    __syncthreads();
    if (wid == 0) {
        int w = wsum[lane];
        int wi = w;
        #pragma unroll
        for (int d = 1; d < 32; d <<= 1) {
            int u = __shfl_up_sync(0xffffffffu, wi, d);
            if (lane >= d) wi += u;
        }
        wsum[lane] = wi - w;
    }
    __syncthreads();
    int pre = tilepre + wsum[wid] + incl - ts;
    int p0 = pre, p1 = p0 + v0, p2 = p1 + v1, p3 = p2 + v2;
    if (base + 3 < NN) {
        int4 pv = {p0, p1, p2, p3};
        *(int4*)&g_rowptr[r * RPS + base] = pv;
        *(int4*)&g_wptr[r * NN + base] = pv;
    } else {
        int pp[4] = {p0, p1, p2, p3};
        #pragma unroll
        for (int j = 0; j < 4; j++)
            if (base + j < NN) {
                g_rowptr[r * RPS + base + j] = pp[j];
                g_wptr[r * NN + base + j] = pp[j];
            }
    }
    if (b == NB - 1 && t == 1023) g_rowptr[r * RPS + NN] = tiletot;
}

// ---------------- counting-sort fill: 2 edges/thread, direct slot atomic + int2 store ----------------
__global__ void k_fill(const int2* __restrict__ src2, const int2* __restrict__ dst2) {
    int i = blockIdx.x * blockDim.x + threadIdx.x;
    int r = blockIdx.y;
    if (i < EE / 2) {
        int2 s2 = __ldg(&src2[(size_t)r * (EE / 2) + i]);
        int2 d2 = __ldg(&dst2[(size_t)r * (EE / 2) + i]);
        {
            int pos = atomicAdd(&g_wptr[r * NN + d2.x], 1);
            float no = rsqrtf(fmaxf((float)ODEG(r, s2.x), 1.f));
            float ni = rsqrtf(fmaxf((float)IDEG(r, d2.x), 1.f));
            int2 ev = { s2.x * 32, __float_as_int(no * ni * (1.f / 3.f)) };
            g_edge[(size_t)r * EE + pos] = ev;
        }
        {
            int pos = atomicAdd(&g_wptr[r * NN + d2.y], 1);
            float no = rsqrtf(fmaxf((float)ODEG(r, s2.y), 1.f));
            float ni = rsqrtf(fmaxf((float)IDEG(r, d2.y), 1.f));
            int2 ev = { s2.y * 32, __float_as_int(no * ni * (1.f / 3.f)) };
            g_edge[(size_t)r * EE + pos] = ev;
        }
    }
}

// ---------------- SpMM (proven form): warp-per-row float4 gathers, MLP=8 ----------------
__global__ __launch_bounds__(256) void k_spmm(const float4* __restrict__ h4,
                                              uint2* __restrict__ aggh,
                                              uint2* __restrict__ aggl) {
    int r = blockIdx.y;
    int row = blockIdx.x * 8 + (threadIdx.x >> 5);
    int lane = threadIdx.x & 31;
    if (row >= NN) return;
    int beg = g_rowptr[r * RPS + row];
    int end = g_rowptr[r * RPS + row + 1];
    if (row == NN - 1) end = g_rowptr[r * RPS + NN];
    const int2* ed = &g_edge[(size_t)r * EE];
    float4 acc = {0.f, 0.f, 0.f, 0.f};
    int e = beg;
    for (; e + 8 <= end; e += 8) {
        int2 ev[8]; float4 v[8];
        #pragma unroll
        for (int j = 0; j < 8; j++) ev[j] = __ldg(&ed[e + j]);
        #pragma unroll
        for (int j = 0; j < 8; j++) v[j] = __ldg(&h4[ev[j].x + lane]);
        #pragma unroll
        for (int j = 0; j < 8; j++) {
            float c = __int_as_float(ev[j].y);
            acc.x += c * v[j].x;
            acc.y += c * v[j].y;
            acc.z += c * v[j].z;
            acc.w += c * v[j].w;
        }
    }
    if (e + 4 <= end) {
        int2 ev[4]; float4 v[4];
        #pragma unroll
        for (int j = 0; j < 4; j++) ev[j] = __ldg(&ed[e + j]);
        #pragma unroll
        for (int j = 0; j < 4; j++) v[j] = __ldg(&h4[ev[j].x + lane]);
        #pragma unroll
        for (int j = 0; j < 4; j++) {
            float c = __int_as_float(ev[j].y);
            acc.x += c * v[j].x;
            acc.y += c * v[j].y;
            acc.z += c * v[j].z;
            acc.w += c * v[j].w;
        }
        e += 4;
    }
    for (; e < end; e++) {
        int2 ev = __ldg(&ed[e]);
        float c = __int_as_float(ev.y);
        float4 v = __ldg(&h4[ev.x + lane]);
        acc.x += c * v.x; acc.y += c * v.y; acc.z += c * v.z; acc.w += c * v.w;
    }
    __nv_bfloat162 h01(__float2bfloat16(acc.x), __float2bfloat16(acc.y));
    __nv_bfloat162 h23(__float2bfloat16(acc.z), __float2bfloat16(acc.w));
    __nv_bfloat162 l01(__float2bfloat16(acc.x - __bfloat162float(h01.x)),
                       __float2bfloat16(acc.y - __bfloat162float(h01.y)));
    __nv_bfloat162 l23(__float2bfloat16(acc.z - __bfloat162float(h23.x)),
                       __float2bfloat16(acc.w - __bfloat162float(h23.y)));
    size_t idx = ((size_t)r * NP + row) * 32 + lane;
    uint2 hv = { *reinterpret_cast<uint32_t*>(&h01), *reinterpret_cast<uint32_t*>(&h23) };
    uint2 lv = { *reinterpret_cast<uint32_t*>(&l01), *reinterpret_cast<uint32_t*>(&l23) };
    aggh[idx] = hv;
    aggl[idx] = lv;
}

// ---------------- mma.sync GEMM: C[M,BN] = A[M,32*KITER] @ W, bf16 hi/lo split ----------------
// A (bf16) layout: A[((k>>7)*NP + row)*128 + (k&127)]  (relation-chunked concat)
// B (bf16) row-major [K][BN]. 512 threads, BM=128, warp grid 4x4. bias prefolded.
template <int BN, int KITER, bool RELU>
__global__ __launch_bounds__(512) void k_mgemm(const __nv_bfloat16* __restrict__ Ah,
                                               const __nv_bfloat16* __restrict__ Al,
                                               const __nv_bfloat16* __restrict__ Bh,
                                               const __nv_bfloat16* __restrict__ Bl,
                                               const float* __restrict__ bias,
                                               float* __restrict__ C, int M) {
    constexpr int APITCH = 40;                 // bf16 units (80B rows: conflict-free ldsm)
    constexpr int BPITCH = BN + 8;
    constexpr int ASZ = 128 * APITCH * 2;
    constexpr int BSZ = 32 * BPITCH * 2;
    constexpr int STG = 2 * ASZ + 2 * BSZ;
    constexpr int WN = BN / 4;
    constexpr int NT = WN / 8;
    constexpr int NSEG = BN / 8;

    extern __shared__ char smem[];
    uint32_t sb = smem_u32(smem);
    const int tid = threadIdx.x;
    const int wid = tid >> 5, lane = tid & 31;
    const int warp_row = wid >> 2, warp_col = wid & 3;
    const int blockRow = blockIdx.x * 128;

    auto load_chunk = [&](int it, int s) {
        uint32_t stg = sb + s * STG;
        int kg = it * 32;
        int rel = kg >> 7, kloc = kg & 127;
        int arow = tid >> 2, aseg = tid & 3;
        size_t abase = ((size_t)rel * NP + blockRow + arow) * 128 + kloc + aseg * 8;
        uint32_t ad = stg + (arow * APITCH + aseg * 8) * 2;
        cpasync16(ad,       Ah + abase);
        cpasync16(ad + ASZ, Al + abase);
        if (tid < 32 * NSEG) {
            int brow = tid / NSEG, bseg = tid % NSEG;
            size_t bbase = (size_t)(kg + brow) * BN + bseg * 8;
            uint32_t bd = stg + 2 * ASZ + (brow * BPITCH + bseg * 8) * 2;
            cpasync16(bd,       Bh + bbase);
            cpasync16(bd + BSZ, Bl + bbase);
        }
    };

    float acc[2][NT][4];
    #pragma unroll
    for (int mt = 0; mt < 2; mt++)
        #pragma unroll
        for (int nt = 0; nt < NT; nt++)
            #pragma unroll
            for (int j = 0; j < 4; j++) acc[mt][nt][j] = 0.f;

    load_chunk(0, 0);
    cp_commit();

    #pragma unroll 1
    for (int it = 0; it < KITER; it++) {
        if (it + 1 < KITER) {
            load_chunk(it + 1, (it + 1) & 1);
            cp_commit();
            cp_wait<1>();
        } else {
            cp_wait<0>();
        }
        __syncthreads();
        uint32_t sA  = sb + (it & 1) * STG;
        uint32_t sB  = sA + 2 * ASZ;
        #pragma unroll
        for (int ks = 0; ks < 2; ks++) {
            uint32_t ah[2][4], al_[2][4];
            #pragma unroll
            for (int mt = 0; mt < 2; mt++) {
                uint32_t ad = sA + ((warp_row * 32 + mt * 16 + (lane & 15)) * APITCH +
                                    ks * 16 + (lane >> 4) * 8) * 2;
                ldsm_x4(ah[mt], ad);
                ldsm_x4(al_[mt], ad + ASZ);
            }
            uint32_t bh[NT / 2][4], bl[NT / 2][4];
            #pragma unroll
            for (int p = 0; p < NT / 2; p++) {
                uint32_t bd = sB + ((ks * 16 + (lane & 15)) * BPITCH +
                                    warp_col * WN + p * 16 + (lane >> 4) * 8) * 2;
                ldsm_x4t(bh[p], bd);
                ldsm_x4t(bl[p], bd + BSZ);
            }
            #pragma unroll
            for (int mt = 0; mt < 2; mt++)
                #pragma unroll
                for (int nt = 0; nt < NT; nt++) {
                    const uint32_t* bhp = &bh[nt >> 1][(nt & 1) * 2];
                    const uint32_t* blp = &bl[nt >> 1][(nt & 1) * 2];
                    mma16816(acc[mt][nt], ah[mt], bhp);
                    mma16816(acc[mt][nt], ah[mt], blp);
                    mma16816(acc[mt][nt], al_[mt], bhp);
                }
        }
        __syncthreads();
    }

    // epilogue: prefolded bias + leaky-relu + store
    const int lane4 = lane >> 2, lane2 = lane & 3;
    #pragma unroll
    for (int mt = 0; mt < 2; mt++) {
        int row0 = blockRow + warp_row * 32 + mt * 16 + lane4;
        #pragma unroll
        for (int nt = 0; nt < NT; nt++) {
            int col = warp_col * WN + nt * 8 + lane2 * 2;
            float2 bb = *reinterpret_cast<const float2*>(&bias[col]);
            #pragma unroll
            for (int h = 0; h < 2; h++) {
                int row = row0 + h * 8;
                if (row < M) {
                    float v0 = acc[mt][nt][h * 2 + 0] + bb.x;
                    float v1 = acc[mt][nt][h * 2 + 1] + bb.y;
                    if (RELU) {
                        v0 = (v0 > 0.f) ? v0 : 0.01f * v0;
                        v1 = (v1 > 0.f) ? v1 : 0.01f * v1;
                    }
                    float2 v = {v0, v1};
                    *reinterpret_cast<float2*>(&C[(size_t)row * BN + col]) = v;
                }
            }
        }
    }
}

// ---------------- launch ----------------
extern "C" void kernel_launch(void* const* d_in, const int* in_sizes, int n_in,
                              void* d_out, int out_size) {
    const float* x    = (const float*)d_in[0];
    const int*   esrc = (const int*)  d_in[1];
    const int*   edst = (const int*)  d_in[2];
    const float* W0   = (const float*)d_in[3];
    const float* b0   = (const float*)d_in[4];
    const float* Wl   = (const float*)d_in[5];
    const float* bl   = (const float*)d_in[6];
    const float* Wout = (const float*)d_in[7];
    const float* bout = (const float*)d_in[8];
    float* out = (float*)d_out;

    void *p_h0, *p_h1, *p_aggh, *p_aggl, *p_wh, *p_wl, *p_bm, *p_bf;
    cudaGetSymbolAddress(&p_h0, g_h0);
    cudaGetSymbolAddress(&p_h1, g_h1);
    cudaGetSymbolAddress(&p_aggh, g_aggh);
    cudaGetSymbolAddress(&p_aggl, g_aggl);
    cudaGetSymbolAddress(&p_wh, g_wh);
    cudaGetSymbolAddress(&p_wl, g_wl);
    cudaGetSymbolAddress(&p_bm, g_biasm);
    cudaGetSymbolAddress(&p_bf, g_biasf);

    cudaFuncSetAttribute(k_mgemm<128, 12, true >, cudaFuncAttributeMaxDynamicSharedMemorySize, 75776);
    cudaFuncSetAttribute(k_mgemm<64,  12, false>, cudaFuncAttributeMaxDynamicSharedMemorySize, 59392);

    k_prep<<<(PREP_TOT + 255) / 256, 256>>>(W0, Wl, Wout, b0, bl, bout);

    dim3 gd((EE / 4 + 255) / 256, RR);
    k_degree<<<gd, 256>>>((const int4*)esrc, (const int4*)edst);
    dim3 gsn(NB, RR);
    k_scan1<<<gsn, 1024>>>();
    k_scan3<<<gsn, 1024>>>();
    dim3 ge((EE / 2 + 255) / 256, RR);
    k_fill<<<ge, 256>>>((const int2*)esrc, (const int2*)edst);

    float4* hbuf[2] = { (float4*)p_h0, (float4*)p_h1 };
    uint2* aggh = (uint2*)p_aggh;
    uint2* aggl = (uint2*)p_aggl;
    const __nv_bfloat16* wh = (const __nv_bfloat16*)p_wh;
    const __nv_bfloat16* wl = (const __nv_bfloat16*)p_wl;
    const float* biasm = (const float*)p_bm;

    dim3 gs((NN + 7) / 8, RR);
    const int GB = (NN + 127) / 128;   // 391

    const float4* cur = (const float4*)x;
    for (int l = 0; l < 4; l++) {
        k_spmm<<<gs, 256>>>(cur, aggh, aggl);
        float* hout = (float*)hbuf[l & 1];
        k_mgemm<128, 12, true><<<GB, 512, 75776>>>(
            (const __nv_bfloat16*)aggh, (const __nv_bfloat16*)aggl,
            wh + (size_t)l * WLAYER, wl + (size_t)l * WLAYER, biasm + l * FD,
            hout, NN);
        cur = (const float4*)hout;
    }

    // layer 4 fused with final Linear: out = agg @ (W4cat @ Wout) + biasf
    k_spmm<<<gs, 256>>>(cur, aggh, aggl);
    k_mgemm<64, 12, false><<<GB, 512, 59392>>>(
        (const __nv_bfloat16*)aggh, (const __nv_bfloat16*)aggl,
        wh + WHID, wl + WHID, (const float*)p_bf,
        out, NN);
}